// round 3
// baseline (speedup 1.0000x reference)
#include <cuda_runtime.h>
#include <cstdint>

#define TLEN   8192
#define BATCH  128
#define NS     128
#define EMITN  64
#define NT     512

// ---- packed f32x2 helpers (sm_103a) ----
__device__ __forceinline__ void fma2(unsigned long long& d, unsigned long long a, unsigned long long b) {
    asm("fma.rn.f32x2 %0, %1, %2, %0;" : "+l"(d) : "l"(a), "l"(b));
}
__device__ __forceinline__ unsigned long long mul2(unsigned long long a, unsigned long long b) {
    unsigned long long d;
    asm("mul.rn.f32x2 %0, %1, %2;" : "=l"(d) : "l"(a), "l"(b));
    return d;
}
__device__ __forceinline__ unsigned long long padd(unsigned long long a, unsigned long long b) {
    unsigned long long d;
    asm("add.rn.f32x2 %0, %1, %2;" : "=l"(d) : "l"(a), "l"(b));
    return d;
}
__device__ __forceinline__ unsigned long long pk(float lo, float hi) {
    unsigned long long r;
    asm("mov.b64 %0, {%1, %2};" : "=l"(r) : "f"(lo), "f"(hi));
    return r;
}
__device__ __forceinline__ float hsum2(unsigned long long v) {
    float lo, hi;
    asm("mov.b64 {%0, %1}, %2;" : "=f"(lo), "=f"(hi) : "l"(v));
    return lo + hi;
}

__global__ __launch_bounds__(NT, 1)
void hmm_forward_kernel(const float* __restrict__ inputs,
                        const float* __restrict__ Ivec,
                        const float* __restrict__ Amat,
                        const float* __restrict__ Bmat,
                        float* __restrict__ out)
{
    __shared__ float Bsh[EMITN * NS];                       // 32 KB
    __shared__ unsigned char obs_sm[TLEN];                  // 8 KB
    __shared__ __align__(16) float ubuf[NS];                // v_t (pow2-scaled alpha)
    __shared__ __align__(16) unsigned long long rpartU[4][NS];  // per-quarter partial dots (f32x2)
    __shared__ __align__(16) float zw[2][4];                // stale sums (double-buffered)
    __shared__ __align__(16) float znext[4];

    const int tid  = threadIdx.x;
    const int s    = tid & 127;     // output state
    const int q    = tid >> 7;      // k-quarter: k in [32q, 32q+32)
    const int w    = tid >> 5;
    const int lane = tid & 31;
    const int b    = blockIdx.x;

    // ---- prologue: B into smem ----
    for (int i = tid; i < EMITN * NS; i += NT) Bsh[i] = Bmat[i];

    // ---- prologue: one-hot -> obs index (exact dot with iota) ----
    {
        const float* xin = inputs + (size_t)b * TLEN * EMITN;
        for (int t = tid; t < TLEN; t += NT) {
            const float4* r = (const float4*)(xin + (size_t)t * EMITN);
            float idx = 0.0f;
            #pragma unroll
            for (int j = 0; j < 16; j++) {
                float4 v = r[j];
                idx = fmaf((float)(4 * j + 0), v.x, idx);
                idx = fmaf((float)(4 * j + 1), v.y, idx);
                idx = fmaf((float)(4 * j + 2), v.z, idx);
                idx = fmaf((float)(4 * j + 3), v.w, idx);
            }
            obs_sm[t] = (unsigned char)__float2int_rn(idx);
        }
    }

    // ---- prologue: A[k][s] for k in [32q, 32q+32) -> 16 packed u64 ----
    unsigned long long Ar[16];
    {
        const int k0 = 32 * q;
        #pragma unroll
        for (int j = 0; j < 16; j++) {
            float a0 = Amat[(k0 + 2 * j) * NS + s];
            float a1 = Amat[(k0 + 2 * j + 1) * NS + s];
            Ar[j] = pk(a0, a1);
        }
    }
    float Ival = Ivec[s];
    __syncthreads();

    // ---- t = 0: v0 = E0 * I ----
    {
        int o0 = obs_sm[0];
        float v0 = Bsh[o0 * NS + s] * Ival;
        if (q == 0) ubuf[s] = v0;
    }
    __syncthreads();

    // ---- init stale-sum buffer zw[0] = sum(v_0) (warp 0) ----
    if (w == 0) {
        float vs = (ubuf[lane] + ubuf[lane + 32]) + (ubuf[lane + 64] + ubuf[lane + 96]);
        #pragma unroll
        for (int off = 16; off > 0; off >>= 1) vs += __shfl_xor_sync(0xffffffffu, vs, off);
        if (lane == 0) { zw[0][0] = vs; zw[0][1] = 0.f; zw[0][2] = 0.f; zw[0][3] = 0.f; }
    }
    __syncthreads();

    int   Stot  = 0;       // accumulated power-of-2 exponent (valid on q==0 threads)
    float Elast = 0.f, Rlast = 0.f;

    // ---- main recurrence ----
    for (int t = 1; t < TLEN; t++) {
        // ===== FMA phase: partial dot over this thread's k-quarter =====
        // FIX (R2): quarter q = ulonglong2 elements [8q, 8q+8) of ubuf (was 4q: wrong overlap)
        const ulonglong2* up = (const ulonglong2*)ubuf + 8 * q;
        ulonglong2 c0 = up[0], c1 = up[1], c2 = up[2], c3 = up[3];

        unsigned long long acc0 = mul2(c0.x, Ar[0]);
        unsigned long long acc1 = mul2(c0.y, Ar[1]);
        unsigned long long acc2 = mul2(c1.x, Ar[2]);
        unsigned long long acc3 = mul2(c1.y, Ar[3]);
        fma2(acc0, c2.x, Ar[4]);  fma2(acc1, c2.y, Ar[5]);
        fma2(acc2, c3.x, Ar[6]);  fma2(acc3, c3.y, Ar[7]);

        float E;
        if (q == 0) {            // prefetch emission for the combine phase
            int o = obs_sm[t];
            E = Bsh[o * NS + s];
        }

        ulonglong2 c4 = up[4], c5 = up[5], c6 = up[6], c7 = up[7];
        fma2(acc0, c4.x, Ar[8]);   fma2(acc1, c4.y, Ar[9]);
        fma2(acc2, c5.x, Ar[10]);  fma2(acc3, c5.y, Ar[11]);
        fma2(acc0, c6.x, Ar[12]);  fma2(acc1, c6.y, Ar[13]);
        fma2(acc2, c7.x, Ar[14]);  fma2(acc3, c7.y, Ar[15]);

        unsigned long long pp = padd(padd(acc0, acc1), padd(acc2, acc3));
        rpartU[q][s] = pp;        // STS.64, conflict-free

        __syncthreads();          // BAR1: rpart ready

        // ===== combine phase (role-split) =====
        if (q == 0) {
            // 2-step-stale sum -> damped exact-pow2 rescale: e = floor(log2(Z)/2)
            // (beta=1/2 feedback: roots (1+-i)/2, |z|=0.707 -> exponent drift damped)
            float4 zp = *(const float4*)zw[(t - 1) & 1];
            float Z = (zp.x + zp.y) + (zp.z + zp.w);
            int xe = ((__float_as_int(Z) >> 23) & 255) - 127;
            int e  = xe >> 1;                                 // floor(x/2), arith shift
            Stot += e;
            float scalef = __int_as_float((127 - e) << 23);   // 2^{-e}, exact

            // own quarter's partial is still in pp (no reload of rpartU[0])
            float2 r1 = *(const float2*)&rpartU[1][s];
            float2 r2 = *(const float2*)&rpartU[2][s];
            float2 r3 = *(const float2*)&rpartU[3][s];
            float R = (hsum2(pp) + (r1.x + r1.y)) + ((r2.x + r2.y) + (r3.x + r3.y));

            float vnew = (E * scalef) * R;
            ubuf[s] = vnew;
            Elast = E; Rlast = R;
        } else if (q == 1) {
            // stale-sum producer for step t+2:
            // sum over ALL rpart = sum_s R_t[s] = sum_k v_{t-1}[k]  (A rows sum to 1)
            const float4* rp4 = (const float4*)rpartU;   // 1024 floats = 256 float4
            float4 a  = rp4[2 * s];
            float4 bb = rp4[2 * s + 1];
            float zs = ((a.x + a.y) + (a.z + a.w)) + ((bb.x + bb.y) + (bb.z + bb.w));
            #pragma unroll
            for (int off = 16; off > 0; off >>= 1) zs += __shfl_xor_sync(0xffffffffu, zs, off);
            if (lane == 0) zw[t & 1][w & 3] = zs;
        }
        __syncthreads();          // BAR2: ubuf(t) + zw ready
    }

    // ---- epilogue ----
    // sum(v_{T-1}) via row-sum identity: sum_s R_T[s]
    if (q == 0) {
        float rr = Rlast;
        #pragma unroll
        for (int off = 16; off > 0; off >>= 1) rr += __shfl_xor_sync(0xffffffffu, rr, off);
        if (lane == 0) znext[w] = rr;
    }
    __syncthreads();

    if (q == 0) {
        float4 zn = *(const float4*)znext;
        float ZT1 = (zn.x + zn.y) + (zn.z + zn.w);     // = sum(v_{T-1})
        out[b * NS + s] = Elast * Rlast / ZT1;         // alpha_f (pow2 factors cancel)
    }

    if (w == 0) {
        float vT = (ubuf[lane] + ubuf[lane + 32]) + (ubuf[lane + 64] + ubuf[lane + 96]);
        #pragma unroll
        for (int off = 16; off > 0; off >>= 1) vT += __shfl_xor_sync(0xffffffffu, vT, off);
        if (lane == 0) {
            double ll = log((double)vT) + (double)Stot * 0.6931471805599453;
            out[BATCH * NS + b] = (float)ll;           // loglik
        }
    }
}

extern "C" void kernel_launch(void* const* d_in, const int* in_sizes, int n_in,
                              void* d_out, int out_size)
{
    const float* inputs = (const float*)d_in[0];   // [128, 8192, 64]
    const float* Ivec   = (const float*)d_in[1];   // [128]
    const float* Amat   = (const float*)d_in[2];   // [128, 128]
    const float* Bmat   = (const float*)d_in[3];   // [64, 128]
    float* out = (float*)d_out;                    // alpha_f [128,128] ++ loglik [128]

    hmm_forward_kernel<<<BATCH, NT>>>(inputs, Ivec, Amat, Bmat, out);
}